// round 3
// baseline (speedup 1.0000x reference)
#include <cuda_runtime.h>
#include <cstdint>

#define N_B    16
#define C_CH   512
#define W_LEN  4096
#define NUM_MASKED 1024          // NUM_MASKS * MASK_WIDTH
#define M_ROWS 11264             // 1024 masked + 10240 negative rows
#define FD     512
#define OUT_MAIN_ELEMS ((size_t)N_B * C_CH * W_LEN)   // 33,554,432

// Scratch (device globals only — no allocation allowed)
__device__ float g_A[(size_t)M_ROWS * C_CH];                 // gathered GEMM A matrix
__device__ __align__(128) signed char g_slot[N_B * W_LEN];   // (b,t) -> mask row (0..3) or -1

// ---------------------------------------------------------------------------
// Slot table init: all -1
// ---------------------------------------------------------------------------
__global__ void k_init_slot() {
    int i = blockIdx.x * blockDim.x + threadIdx.x;   // 16384 int writes
    if (i < (N_B * W_LEN) / 4) ((int*)g_slot)[i] = -1;
}

// Scatter mask rows: slot[pack_idx[masked_idx[j]]] = j & 3
__global__ void k_scatter_slot(const int* __restrict__ masked_idx,
                               const int* __restrict__ pack_idx) {
    int j = blockIdx.x * blockDim.x + threadIdx.x;
    if (j < NUM_MASKED) {
        int flat = pack_idx[masked_idx[j]];
        g_slot[flat] = (signed char)(j & 3);
    }
}

// ---------------------------------------------------------------------------
// Gather GEMM A rows: A[m, c] = inputs[b, c, t] (channel stride W -> scattered)
// ---------------------------------------------------------------------------
__global__ void k_gather(const float* __restrict__ inp,
                         const int* __restrict__ pack_idx,
                         const int* __restrict__ masked_idx,
                         const int* __restrict__ neg_idx) {
    int m = blockIdx.x;
    int sel = (m < NUM_MASKED) ? masked_idx[m] : neg_idx[m - NUM_MASKED];
    int flat = pack_idx[sel];
    int b = flat >> 12;               // W = 4096
    int t = flat & (W_LEN - 1);
    const float* src = inp + (size_t)b * C_CH * W_LEN + t;
    float* dst = g_A + (size_t)m * C_CH;
    #pragma unroll
    for (int c = threadIdx.x; c < C_CH; c += 128)
        dst[c] = __ldg(src + (size_t)c * W_LEN);
}

// ---------------------------------------------------------------------------
// Main output: coalesced float4 copy with length-zeroing + mask overwrite
// ---------------------------------------------------------------------------
__global__ void k_copy(const float4* __restrict__ inp4,
                       const int* __restrict__ seq_len,
                       const float* __restrict__ mask_emb,
                       float4* __restrict__ out4) {
    int i4 = blockIdx.x * blockDim.x + threadIdx.x;
    long i = (long)i4 * 4;                       // flat index into (b, c, t)
    int t = (int)(i & (W_LEN - 1));
    int c = (int)((i >> 12) & (C_CH - 1));
    int b = (int)(i >> 21);                      // C*W = 2^21
    int len = __ldg(seq_len + b);

    float4 v = inp4[i4];
    if (t + 3 >= len) {                          // zero padded tail
        if (t + 0 >= len) v.x = 0.f;
        if (t + 1 >= len) v.y = 0.f;
        if (t + 2 >= len) v.z = 0.f;
        if (t + 3 >= len) v.w = 0.f;
    }
    int ss = *(const int*)(g_slot + b * W_LEN + t);   // 4 slot bytes (t aligned to 4)
    if (ss != -1) {                              // rare path (~1.6% of (b,t))
        signed char s0 = (signed char)(ss);
        signed char s1 = (signed char)(ss >> 8);
        signed char s2 = (signed char)(ss >> 16);
        signed char s3 = (signed char)(ss >> 24);
        if (s0 >= 0) v.x = __ldg(mask_emb + s0 * C_CH + c);
        if (s1 >= 0) v.y = __ldg(mask_emb + s1 * C_CH + c);
        if (s2 >= 0) v.z = __ldg(mask_emb + s2 * C_CH + c);
        if (s3 >= 0) v.w = __ldg(mask_emb + s3 * C_CH + c);
    }
    out4[i4] = v;
}

// ---------------------------------------------------------------------------
// fp32 SGEMM: res[m, f] = sum_k A[m,k] * Wq[f,k] + bq[f]
// BM=64, BN=128, BK=16, 256 threads, per-thread 4x8 micro-tile
// ---------------------------------------------------------------------------
#define BM 64
#define BN 128
#define BK 16

__global__ void __launch_bounds__(256) k_gemm(const float* __restrict__ Wq,
                                              const float* __restrict__ bq,
                                              float* __restrict__ res) {
    __shared__ float As[BK][BM];
    __shared__ float Bs[BK][BN];

    const int tid = threadIdx.x;
    const int m0 = blockIdx.x * BM;
    const int f0 = blockIdx.y * BN;
    const int tx = tid & 15;    // n-dir (8 cols each)
    const int ty = tid >> 4;    // m-dir (4 rows each)

    const int r  = tid >> 2;           // 0..63
    const int kc = (tid & 3) << 2;     // 0,4,8,12

    const float* Aptr = g_A + (size_t)m0 * FD;
    const float* Bptr = Wq  + (size_t)f0 * FD;

    float acc[4][8];
    #pragma unroll
    for (int i = 0; i < 4; i++)
        #pragma unroll
        for (int j = 0; j < 8; j++) acc[i][j] = 0.f;

    for (int k0 = 0; k0 < FD; k0 += BK) {
        float4 av  = *(const float4*)(Aptr + (size_t)r        * FD + k0 + kc);
        float4 bv0 = *(const float4*)(Bptr + (size_t)r        * FD + k0 + kc);
        float4 bv1 = *(const float4*)(Bptr + (size_t)(r + 64) * FD + k0 + kc);
        __syncthreads();   // previous tile fully consumed
        As[kc+0][r] = av.x;  As[kc+1][r] = av.y;  As[kc+2][r] = av.z;  As[kc+3][r] = av.w;
        Bs[kc+0][r] = bv0.x; Bs[kc+1][r] = bv0.y; Bs[kc+2][r] = bv0.z; Bs[kc+3][r] = bv0.w;
        Bs[kc+0][r+64] = bv1.x; Bs[kc+1][r+64] = bv1.y; Bs[kc+2][r+64] = bv1.z; Bs[kc+3][r+64] = bv1.w;
        __syncthreads();

        #pragma unroll
        for (int kk = 0; kk < BK; kk++) {
            float a[4], b[8];
            #pragma unroll
            for (int i = 0; i < 4; i++) a[i] = As[kk][ty * 4 + i];
            #pragma unroll
            for (int j = 0; j < 8; j++) b[j] = Bs[kk][tx * 8 + j];
            #pragma unroll
            for (int i = 0; i < 4; i++)
                #pragma unroll
                for (int j = 0; j < 8; j++)
                    acc[i][j] += a[i] * b[j];
        }
    }

    float bias[8];
    #pragma unroll
    for (int j = 0; j < 8; j++) bias[j] = __ldg(bq + f0 + tx * 8 + j);

    #pragma unroll
    for (int i = 0; i < 4; i++) {
        int m = m0 + ty * 4 + i;
        float* dst = res + (size_t)m * FD + f0 + tx * 8;
        float4 o0 = make_float4(acc[i][0] + bias[0], acc[i][1] + bias[1],
                                acc[i][2] + bias[2], acc[i][3] + bias[3]);
        float4 o1 = make_float4(acc[i][4] + bias[4], acc[i][5] + bias[5],
                                acc[i][6] + bias[6], acc[i][7] + bias[7]);
        *(float4*)(dst)     = o0;
        *(float4*)(dst + 4) = o1;
    }
}

// ---------------------------------------------------------------------------
extern "C" void kernel_launch(void* const* d_in, const int* in_sizes, int n_in,
                              void* d_out, int out_size) {
    (void)in_sizes; (void)n_in; (void)out_size;
    const float* inputs     = (const float*)d_in[0];
    const int*   seq_len    = (const int*)  d_in[1];
    const int*   pack_idx   = (const int*)  d_in[2];
    const int*   masked_idx = (const int*)  d_in[3];
    const int*   neg_idx    = (const int*)  d_in[4];
    const float* mask_emb   = (const float*)d_in[5];
    const float* Wq         = (const float*)d_in[6];
    const float* bq         = (const float*)d_in[7];

    float* out = (float*)d_out;
    float* res = out + OUT_MAIN_ELEMS;   // unmasked (1024x512) then negatives (10240x512), contiguous

    k_init_slot<<<64, 256>>>();
    k_scatter_slot<<<4, 256>>>(masked_idx, pack_idx);
    k_gather<<<M_ROWS, 128>>>(inputs, pack_idx, masked_idx, neg_idx);

    int total4 = (int)(OUT_MAIN_ELEMS / 4);
    k_copy<<<(total4 + 255) / 256, 256>>>((const float4*)inputs, seq_len, mask_emb,
                                          (float4*)d_out);

    dim3 grid(M_ROWS / BM, FD / BN);
    k_gemm<<<grid, 256>>>(Wq, bq, res);
}

// round 4
// speedup vs baseline: 2.4015x; 2.4015x over previous
#include <cuda_runtime.h>
#include <cstdint>

#define N_B    16
#define C_CH   512
#define W_LEN  4096
#define NUM_MASKED 1024          // NUM_MASKS * MASK_WIDTH
#define M_ROWS 11264             // 1024 masked + 10240 negative rows
#define FD     512
#define OUT_MAIN_ELEMS ((size_t)N_B * C_CH * W_LEN)   // 33,554,432

// Scratch (device globals only — no allocation allowed)
__device__ float g_A[(size_t)M_ROWS * FD];                   // gathered A (tf32-rounded)
__device__ float g_B[(size_t)FD * FD];                       // Wq (tf32-rounded)
__device__ __align__(128) signed char g_slot[N_B * W_LEN];   // (b,t) -> mask row (0..3) or -1

__device__ __forceinline__ float tf32r(float x) {
    float y;
    asm("cvt.rna.tf32.f32 %0, %1;" : "=f"(y) : "f"(x));
    return y;
}

// ---------------------------------------------------------------------------
// Slot table init: all -1
// ---------------------------------------------------------------------------
__global__ void k_init_slot() {
    int i = blockIdx.x * blockDim.x + threadIdx.x;   // 16384 int writes
    if (i < (N_B * W_LEN) / 4) ((int*)g_slot)[i] = -1;
}

// Scatter mask rows: slot[pack_idx[masked_idx[j]]] = j & 3
__global__ void k_scatter_slot(const int* __restrict__ masked_idx,
                               const int* __restrict__ pack_idx) {
    int j = blockIdx.x * blockDim.x + threadIdx.x;
    if (j < NUM_MASKED) {
        int flat = pack_idx[masked_idx[j]];
        g_slot[flat] = (signed char)(j & 3);
    }
}

// Pre-round Wq to tf32
__global__ void k_prep_B(const float* __restrict__ Wq) {
    int i = blockIdx.x * blockDim.x + threadIdx.x;
    if (i < FD * FD) g_B[i] = tf32r(Wq[i]);
}

// ---------------------------------------------------------------------------
// Gather GEMM A rows: A[m, c] = tf32(inputs[b, c, t])  (channel stride W)
// ---------------------------------------------------------------------------
__global__ void k_gather(const float* __restrict__ inp,
                         const int* __restrict__ pack_idx,
                         const int* __restrict__ masked_idx,
                         const int* __restrict__ neg_idx) {
    int m = blockIdx.x;
    int sel = (m < NUM_MASKED) ? masked_idx[m] : neg_idx[m - NUM_MASKED];
    int flat = pack_idx[sel];
    int b = flat >> 12;               // W = 4096
    int t = flat & (W_LEN - 1);
    const float* src = inp + (size_t)b * C_CH * W_LEN + t;
    float* dst = g_A + (size_t)m * FD;
    #pragma unroll
    for (int c = threadIdx.x; c < C_CH; c += 128)
        dst[c] = tf32r(__ldg(src + (size_t)c * W_LEN));
}

// ---------------------------------------------------------------------------
// Main output copy: skip input reads entirely in the padded region.
// len is always a multiple of 128 (and t of 4), so a float4 is all-valid or
// all-padding.
// ---------------------------------------------------------------------------
__global__ void k_copy(const float4* __restrict__ inp4,
                       const int* __restrict__ seq_len,
                       const float* __restrict__ mask_emb,
                       float4* __restrict__ out4) {
    int i4 = blockIdx.x * blockDim.x + threadIdx.x;
    long i = (long)i4 * 4;                       // flat index into (b, c, t)
    int t = (int)(i & (W_LEN - 1));
    int c = (int)((i >> 12) & (C_CH - 1));
    int b = (int)(i >> 21);                      // C*W = 2^21
    int len = __ldg(seq_len + b);

    float4 v;
    if (t < len) {
        v = inp4[i4];
        int ss = *(const int*)(g_slot + b * W_LEN + t);   // 4 slot bytes
        if (ss != -1) {                          // rare (~1.6% of valid (b,t))
            signed char s0 = (signed char)(ss);
            signed char s1 = (signed char)(ss >> 8);
            signed char s2 = (signed char)(ss >> 16);
            signed char s3 = (signed char)(ss >> 24);
            if (s0 >= 0) v.x = __ldg(mask_emb + s0 * C_CH + c);
            if (s1 >= 0) v.y = __ldg(mask_emb + s1 * C_CH + c);
            if (s2 >= 0) v.z = __ldg(mask_emb + s2 * C_CH + c);
            if (s3 >= 0) v.w = __ldg(mask_emb + s3 * C_CH + c);
        }
    } else {
        v = make_float4(0.f, 0.f, 0.f, 0.f);
    }
    out4[i4] = v;
}

// ---------------------------------------------------------------------------
// Tensor-core GEMM (tf32 mma.sync): res[m,f] = sum_k A[m,k]*Wq[f,k] + bq[f]
// CTA tile 128x128, BK=32, 8 warps: warp grid 4(m) x 2(n), warp tile 32x64.
// ---------------------------------------------------------------------------
#define GBK 32

__global__ void __launch_bounds__(256) k_gemm_tc(const float* __restrict__ bq,
                                                 float* __restrict__ res) {
    __shared__ float As[128][GBK + 4];   // pad 4 -> conflict-free frag loads
    __shared__ float Bs[128][GBK + 4];   // Bs[n][k] (Wq is [f][k] row-major)

    const int tid  = threadIdx.x;
    const int warp = tid >> 5, lane = tid & 31;
    const int wm = warp & 3;       // 0..3 -> 32 rows each
    const int wn = warp >> 2;      // 0..1 -> 64 cols each
    const int m0 = blockIdx.x * 128;
    const int f0 = blockIdx.y * 128;

    const float* Ag = g_A + (size_t)m0 * FD;
    const float* Bg = g_B + (size_t)f0 * FD;

    float acc[2][8][4];
    #pragma unroll
    for (int mt = 0; mt < 2; mt++)
        #pragma unroll
        for (int nt = 0; nt < 8; nt++)
            #pragma unroll
            for (int q = 0; q < 4; q++) acc[mt][nt][q] = 0.f;

    const int row = lane >> 2;     // 0..7
    const int col = lane & 3;      // 0..3

    for (int k0 = 0; k0 < FD; k0 += GBK) {
        // global -> regs (128x32 tile = 1024 float4 / 256 threads = 4 each)
        float4 av[4], bv[4];
        #pragma unroll
        for (int p = 0; p < 4; p++) {
            int f  = tid + p * 256;
            int r  = f >> 3;
            int c4 = (f & 7) << 2;
            av[p] = *(const float4*)(Ag + (size_t)r * FD + k0 + c4);
            bv[p] = *(const float4*)(Bg + (size_t)r * FD + k0 + c4);
        }
        __syncthreads();
        #pragma unroll
        for (int p = 0; p < 4; p++) {
            int f  = tid + p * 256;
            int r  = f >> 3;
            int c4 = (f & 7) << 2;
            *(float4*)&As[r][c4] = av[p];
            *(float4*)&Bs[r][c4] = bv[p];
        }
        __syncthreads();

        #pragma unroll
        for (int ks = 0; ks < GBK / 8; ks++) {
            const int kk = ks * 8;
            uint32_t a[2][4], b[8][2];
            #pragma unroll
            for (int mt = 0; mt < 2; mt++) {
                int mb = wm * 32 + mt * 16;
                a[mt][0] = __float_as_uint(As[mb + row    ][kk + col    ]);
                a[mt][1] = __float_as_uint(As[mb + row + 8][kk + col    ]);
                a[mt][2] = __float_as_uint(As[mb + row    ][kk + col + 4]);
                a[mt][3] = __float_as_uint(As[mb + row + 8][kk + col + 4]);
            }
            #pragma unroll
            for (int nt = 0; nt < 8; nt++) {
                int nb = wn * 64 + nt * 8;
                b[nt][0] = __float_as_uint(Bs[nb + row][kk + col    ]);
                b[nt][1] = __float_as_uint(Bs[nb + row][kk + col + 4]);
            }
            #pragma unroll
            for (int mt = 0; mt < 2; mt++)
                #pragma unroll
                for (int nt = 0; nt < 8; nt++) {
                    asm volatile(
                        "mma.sync.aligned.m16n8k8.row.col.f32.tf32.tf32.f32 "
                        "{%0,%1,%2,%3}, {%4,%5,%6,%7}, {%8,%9}, {%0,%1,%2,%3};\n"
                        : "+f"(acc[mt][nt][0]), "+f"(acc[mt][nt][1]),
                          "+f"(acc[mt][nt][2]), "+f"(acc[mt][nt][3])
                        : "r"(a[mt][0]), "r"(a[mt][1]), "r"(a[mt][2]), "r"(a[mt][3]),
                          "r"(b[nt][0]), "r"(b[nt][1]));
                }
        }
    }

    // epilogue: bias + store (C frag: rows {row, row+8}, cols {2c, 2c+1})
    const int colp = (lane & 3) * 2;
    #pragma unroll
    for (int mt = 0; mt < 2; mt++) {
        int m = m0 + wm * 32 + mt * 16 + row;
        #pragma unroll
        for (int nt = 0; nt < 8; nt++) {
            int f = f0 + wn * 64 + nt * 8 + colp;
            float b0 = __ldg(bq + f), b1 = __ldg(bq + f + 1);
            *(float2*)(res + (size_t)m       * FD + f) =
                make_float2(acc[mt][nt][0] + b0, acc[mt][nt][1] + b1);
            *(float2*)(res + (size_t)(m + 8) * FD + f) =
                make_float2(acc[mt][nt][2] + b0, acc[mt][nt][3] + b1);
        }
    }
}

// ---------------------------------------------------------------------------
extern "C" void kernel_launch(void* const* d_in, const int* in_sizes, int n_in,
                              void* d_out, int out_size) {
    (void)in_sizes; (void)n_in; (void)out_size;
    const float* inputs     = (const float*)d_in[0];
    const int*   seq_len    = (const int*)  d_in[1];
    const int*   pack_idx   = (const int*)  d_in[2];
    const int*   masked_idx = (const int*)  d_in[3];
    const int*   neg_idx    = (const int*)  d_in[4];
    const float* mask_emb   = (const float*)d_in[5];
    const float* Wq         = (const float*)d_in[6];
    const float* bq         = (const float*)d_in[7];

    float* out = (float*)d_out;
    float* res = out + OUT_MAIN_ELEMS;   // unmasked (1024x512) then negatives (10240x512)

    k_init_slot<<<64, 256>>>();
    k_scatter_slot<<<4, 256>>>(masked_idx, pack_idx);
    k_prep_B<<<(FD * FD + 255) / 256, 256>>>(Wq);
    k_gather<<<M_ROWS, 128>>>(inputs, pack_idx, masked_idx, neg_idx);

    int total4 = (int)(OUT_MAIN_ELEMS / 4);
    k_copy<<<(total4 + 255) / 256, 256>>>((const float4*)inputs, seq_len, mask_emb,
                                          (float4*)d_out);

    dim3 grid(M_ROWS / 128, FD / 128);
    k_gemm_tc<<<grid, 256>>>(bq, res);
}

// round 5
// speedup vs baseline: 2.5627x; 1.0672x over previous
#include <cuda_runtime.h>
#include <cstdint>

#define N_B    16
#define C_CH   512
#define W_LEN  4096
#define NUM_MASKED 1024          // NUM_MASKS * MASK_WIDTH
#define M_ROWS 11264             // 1024 masked + 10240 negative rows
#define FD     512
#define OUT_MAIN_ELEMS ((size_t)N_B * C_CH * W_LEN)   // 33,554,432
#define TCH 16                   // t-chunk per fused block

// Scratch (device globals only — no allocation allowed)
__device__ float g_A[(size_t)M_ROWS * FD];                   // gathered A (tf32-rounded)
__device__ float g_B[(size_t)FD * FD];                       // Wq (tf32-rounded)
__device__ __align__(128) signed char g_slot[N_B * W_LEN];   // (b,t) -> mask row (0..3) or -1
__device__ int g_row[N_B * W_LEN];                           // (b,t) -> gemm row m or -1

__device__ __forceinline__ float tf32r(float x) {
    float y;
    asm("cvt.rna.tf32.f32 %0, %1;" : "=f"(y) : "f"(x));
    return y;
}

// ---------------------------------------------------------------------------
// Init both lookup tables to -1
// ---------------------------------------------------------------------------
__global__ void k_init() {
    int i = blockIdx.x * blockDim.x + threadIdx.x;
    if (i < N_B * W_LEN) g_row[i] = -1;
    if (i < (N_B * W_LEN) / 4) ((int*)g_slot)[i] = -1;
}

// Scatter: g_row[(b,t)] = m for all 11264 target rows; g_slot for masked rows
__global__ void k_scatter(const int* __restrict__ masked_idx,
                          const int* __restrict__ neg_idx,
                          const int* __restrict__ pack_idx) {
    int m = blockIdx.x * blockDim.x + threadIdx.x;
    if (m < M_ROWS) {
        int sel = (m < NUM_MASKED) ? masked_idx[m] : neg_idx[m - NUM_MASKED];
        int flat = pack_idx[sel];
        g_row[flat] = m;
        if (m < NUM_MASKED) g_slot[flat] = (signed char)(m & 3);
    }
}

// Pre-round Wq to tf32
__global__ void k_prep_B(const float* __restrict__ Wq) {
    int i = blockIdx.x * blockDim.x + threadIdx.x;
    if (i < FD * FD) g_B[i] = tf32r(Wq[i]);
}

// ---------------------------------------------------------------------------
// Fused copy + mask-overwrite + zero-pad + A-gather.
// Block = (b, t-chunk of 16). Loads tile [512 c x 16 t] to smem, streams the
// masked/zeroed version to out, then extracts gather-target columns as
// coalesced rows of g_A.
// ---------------------------------------------------------------------------
__global__ void __launch_bounds__(256) k_fused(const float4* __restrict__ inp4,
                                               const int* __restrict__ seq_len,
                                               const float* __restrict__ mask_emb,
                                               float4* __restrict__ out4) {
    const int b  = blockIdx.y;
    const int t0 = blockIdx.x * TCH;
    const int tid = threadIdx.x;
    const int len = __ldg(seq_len + b);

    if (t0 >= len) {                         // fully padded chunk: zeros only
        const float4 z = make_float4(0.f, 0.f, 0.f, 0.f);
        #pragma unroll
        for (int it = 0; it < 8; it++) {
            int f  = tid + it * 256;         // 2048 float4 slots
            int c  = f >> 2;
            int t4 = f & 3;
            out4[((size_t)b << 19) + ((size_t)c << 10) + (t0 >> 2) + t4] = z;
        }
        return;
    }

    __shared__ float tile[C_CH][TCH + 1];    // stride 17: conflict-free columns

    #pragma unroll
    for (int it = 0; it < 8; it++) {
        int f  = tid + it * 256;
        int c  = f >> 2;                     // 0..511
        int t4 = f & 3;                      // float4 group within chunk
        size_t gi = ((size_t)b << 19) + ((size_t)c << 10) + (t0 >> 2) + t4;
        float4 v = inp4[gi];
        // stash raw values for gather extraction (pre-mask)
        tile[c][t4 * 4 + 0] = v.x;
        tile[c][t4 * 4 + 1] = v.y;
        tile[c][t4 * 4 + 2] = v.z;
        tile[c][t4 * 4 + 3] = v.w;
        // mask overwrite (rare)
        int ss = *(const int*)(g_slot + b * W_LEN + t0 + t4 * 4);
        if (ss != -1) {
            signed char s0 = (signed char)(ss);
            signed char s1 = (signed char)(ss >> 8);
            signed char s2 = (signed char)(ss >> 16);
            signed char s3 = (signed char)(ss >> 24);
            if (s0 >= 0) v.x = __ldg(mask_emb + s0 * C_CH + c);
            if (s1 >= 0) v.y = __ldg(mask_emb + s1 * C_CH + c);
            if (s2 >= 0) v.z = __ldg(mask_emb + s2 * C_CH + c);
            if (s3 >= 0) v.w = __ldg(mask_emb + s3 * C_CH + c);
        }
        out4[gi] = v;
    }
    __syncthreads();

    // extract gather-target columns: coalesced 512-float rows of g_A
    #pragma unroll
    for (int tloc = 0; tloc < TCH; tloc++) {
        int row = __ldg(g_row + b * W_LEN + t0 + tloc);
        if (row >= 0) {
            float* dst = g_A + (size_t)row * FD;
            dst[tid]       = tf32r(tile[tid][tloc]);
            dst[tid + 256] = tf32r(tile[tid + 256][tloc]);
        }
    }
}

// ---------------------------------------------------------------------------
// Tensor-core GEMM (tf32 mma.sync): res[m,f] = sum_k A[m,k]*Wq[f,k] + bq[f]
// CTA tile 128x128, BK=32, 8 warps: warp grid 4(m) x 2(n), warp tile 32x64.
// ---------------------------------------------------------------------------
#define GBK 32

__global__ void __launch_bounds__(256) k_gemm_tc(const float* __restrict__ bq,
                                                 float* __restrict__ res) {
    __shared__ float As[128][GBK + 4];   // pad 4 -> conflict-free frag loads
    __shared__ float Bs[128][GBK + 4];   // Bs[n][k] (Wq is [f][k] row-major)

    const int tid  = threadIdx.x;
    const int warp = tid >> 5, lane = tid & 31;
    const int wm = warp & 3;       // 0..3 -> 32 rows each
    const int wn = warp >> 2;      // 0..1 -> 64 cols each
    const int m0 = blockIdx.x * 128;
    const int f0 = blockIdx.y * 128;

    const float* Ag = g_A + (size_t)m0 * FD;
    const float* Bg = g_B + (size_t)f0 * FD;

    float acc[2][8][4];
    #pragma unroll
    for (int mt = 0; mt < 2; mt++)
        #pragma unroll
        for (int nt = 0; nt < 8; nt++)
            #pragma unroll
            for (int q = 0; q < 4; q++) acc[mt][nt][q] = 0.f;

    const int row = lane >> 2;     // 0..7
    const int col = lane & 3;      // 0..3

    for (int k0 = 0; k0 < FD; k0 += GBK) {
        float4 av[4], bv[4];
        #pragma unroll
        for (int p = 0; p < 4; p++) {
            int f  = tid + p * 256;
            int r  = f >> 3;
            int c4 = (f & 7) << 2;
            av[p] = *(const float4*)(Ag + (size_t)r * FD + k0 + c4);
            bv[p] = *(const float4*)(Bg + (size_t)r * FD + k0 + c4);
        }
        __syncthreads();
        #pragma unroll
        for (int p = 0; p < 4; p++) {
            int f  = tid + p * 256;
            int r  = f >> 3;
            int c4 = (f & 7) << 2;
            *(float4*)&As[r][c4] = av[p];
            *(float4*)&Bs[r][c4] = bv[p];
        }
        __syncthreads();

        #pragma unroll
        for (int ks = 0; ks < GBK / 8; ks++) {
            const int kk = ks * 8;
            uint32_t a[2][4], b[8][2];
            #pragma unroll
            for (int mt = 0; mt < 2; mt++) {
                int mb = wm * 32 + mt * 16;
                a[mt][0] = __float_as_uint(As[mb + row    ][kk + col    ]);
                a[mt][1] = __float_as_uint(As[mb + row + 8][kk + col    ]);
                a[mt][2] = __float_as_uint(As[mb + row    ][kk + col + 4]);
                a[mt][3] = __float_as_uint(As[mb + row + 8][kk + col + 4]);
            }
            #pragma unroll
            for (int nt = 0; nt < 8; nt++) {
                int nb = wn * 64 + nt * 8;
                b[nt][0] = __float_as_uint(Bs[nb + row][kk + col    ]);
                b[nt][1] = __float_as_uint(Bs[nb + row][kk + col + 4]);
            }
            #pragma unroll
            for (int mt = 0; mt < 2; mt++)
                #pragma unroll
                for (int nt = 0; nt < 8; nt++) {
                    asm volatile(
                        "mma.sync.aligned.m16n8k8.row.col.f32.tf32.tf32.f32 "
                        "{%0,%1,%2,%3}, {%4,%5,%6,%7}, {%8,%9}, {%0,%1,%2,%3};\n"
                        : "+f"(acc[mt][nt][0]), "+f"(acc[mt][nt][1]),
                          "+f"(acc[mt][nt][2]), "+f"(acc[mt][nt][3])
                        : "r"(a[mt][0]), "r"(a[mt][1]), "r"(a[mt][2]), "r"(a[mt][3]),
                          "r"(b[nt][0]), "r"(b[nt][1]));
                }
        }
    }

    const int colp = (lane & 3) * 2;
    #pragma unroll
    for (int mt = 0; mt < 2; mt++) {
        int m = m0 + wm * 32 + mt * 16 + row;
        #pragma unroll
        for (int nt = 0; nt < 8; nt++) {
            int f = f0 + wn * 64 + nt * 8 + colp;
            float b0 = __ldg(bq + f), b1 = __ldg(bq + f + 1);
            *(float2*)(res + (size_t)m       * FD + f) =
                make_float2(acc[mt][nt][0] + b0, acc[mt][nt][1] + b1);
            *(float2*)(res + (size_t)(m + 8) * FD + f) =
                make_float2(acc[mt][nt][2] + b0, acc[mt][nt][3] + b1);
        }
    }
}

// ---------------------------------------------------------------------------
extern "C" void kernel_launch(void* const* d_in, const int* in_sizes, int n_in,
                              void* d_out, int out_size) {
    (void)in_sizes; (void)n_in; (void)out_size;
    const float* inputs     = (const float*)d_in[0];
    const int*   seq_len    = (const int*)  d_in[1];
    const int*   pack_idx   = (const int*)  d_in[2];
    const int*   masked_idx = (const int*)  d_in[3];
    const int*   neg_idx    = (const int*)  d_in[4];
    const float* mask_emb   = (const float*)d_in[5];
    const float* Wq         = (const float*)d_in[6];
    const float* bq         = (const float*)d_in[7];

    float* out = (float*)d_out;
    float* res = out + OUT_MAIN_ELEMS;   // unmasked (1024x512) then negatives (10240x512)

    k_init<<<(N_B * W_LEN + 255) / 256, 256>>>();
    k_scatter<<<(M_ROWS + 255) / 256, 256>>>(masked_idx, neg_idx, pack_idx);
    k_prep_B<<<(FD * FD + 255) / 256, 256>>>(Wq);

    dim3 fgrid(W_LEN / TCH, N_B);
    k_fused<<<fgrid, 256>>>((const float4*)inputs, seq_len, mask_emb, (float4*)d_out);

    dim3 grid(M_ROWS / 128, FD / 128);
    k_gemm_tc<<<grid, 256>>>(bq, res);
}

// round 6
// speedup vs baseline: 2.7790x; 1.0844x over previous
#include <cuda_runtime.h>
#include <cstdint>

#define N_B    16
#define C_CH   512
#define W_LEN  4096
#define NUM_MASKED 1024          // NUM_MASKS * MASK_WIDTH
#define M_ROWS 11264             // 1024 masked + 10240 negative rows
#define FD     512
#define OUT_MAIN_ELEMS ((size_t)N_B * C_CH * W_LEN)   // 33,554,432
#define TCH 32                   // t-chunk per fused block

// Scratch (device globals only — no allocation allowed)
__device__ float g_A[(size_t)M_ROWS * FD];                   // gathered A (tf32-rounded)
__device__ float g_B[(size_t)FD * FD];                       // Wq (tf32-rounded)
__device__ __align__(128) signed char g_slot[N_B * W_LEN];   // (b,t) -> mask row (0..3) or -1
__device__ int g_row[N_B * W_LEN];                           // (b,t) -> gemm row m or -1

__device__ __forceinline__ float tf32r(float x) {
    float y;
    asm("cvt.rna.tf32.f32 %0, %1;" : "=f"(y) : "f"(x));
    return y;
}

__device__ __forceinline__ void cp_async16(void* smem_dst, const void* gmem_src) {
    uint32_t s = (uint32_t)__cvta_generic_to_shared(smem_dst);
    asm volatile("cp.async.cg.shared.global [%0], [%1], 16;\n" :: "r"(s), "l"(gmem_src));
}

// ---------------------------------------------------------------------------
// Init both lookup tables to -1
// ---------------------------------------------------------------------------
__global__ void k_init() {
    int i = blockIdx.x * blockDim.x + threadIdx.x;
    if (i < N_B * W_LEN) g_row[i] = -1;
    if (i < (N_B * W_LEN) / 4) ((int*)g_slot)[i] = -1;
}

// Scatter: g_row[(b,t)] = m for all 11264 target rows; g_slot for masked rows
__global__ void k_scatter(const int* __restrict__ masked_idx,
                          const int* __restrict__ neg_idx,
                          const int* __restrict__ pack_idx) {
    int m = blockIdx.x * blockDim.x + threadIdx.x;
    if (m < M_ROWS) {
        int sel = (m < NUM_MASKED) ? masked_idx[m] : neg_idx[m - NUM_MASKED];
        int flat = pack_idx[sel];
        g_row[flat] = m;
        if (m < NUM_MASKED) g_slot[flat] = (signed char)(m & 3);
    }
}

// Pre-round Wq to tf32
__global__ void k_prep_B(const float* __restrict__ Wq) {
    int i = blockIdx.x * blockDim.x + threadIdx.x;
    if (i < FD * FD) g_B[i] = tf32r(Wq[i]);
}

// ---------------------------------------------------------------------------
// Fused copy + mask-overwrite + zero-pad + A-gather.
// Block = (b, 32-t chunk), 512 threads. Loads [512 c x 32 t] to smem, streams
// masked/zeroed version to out, then for each gather target writes one fully
// coalesced 2KB row of g_A (thread == channel).
// ---------------------------------------------------------------------------
__global__ void __launch_bounds__(512) k_fused(const float4* __restrict__ inp4,
                                               const int* __restrict__ seq_len,
                                               const float* __restrict__ mask_emb,
                                               float4* __restrict__ out4) {
    const int b  = blockIdx.y;
    const int t0 = blockIdx.x * TCH;
    const int tid = threadIdx.x;
    const int len = __ldg(seq_len + b);
    const int t4  = tid & 7;                 // float4 group within chunk (fixed)

    if (t0 >= len) {                         // fully padded chunk: zeros only
        const float4 z = make_float4(0.f, 0.f, 0.f, 0.f);
        #pragma unroll
        for (int it = 0; it < 8; it++) {
            int c = (tid >> 3) + it * 64;
            out4[((size_t)b << 19) + ((size_t)c << 10) + (t0 >> 2) + t4] = z;
        }
        return;
    }

    __shared__ float tile[C_CH][TCH + 1];    // stride 33: conflict-free both ways
    __shared__ int rowbuf[TCH];

    if (tid < TCH) rowbuf[tid] = __ldg(g_row + b * W_LEN + t0 + tid);

    // slot word is loop-invariant (t4 fixed per thread) — load once
    const int ss = *(const int*)(g_slot + b * W_LEN + t0 + t4 * 4);
    const signed char s0 = (signed char)(ss);
    const signed char s1 = (signed char)(ss >> 8);
    const signed char s2 = (signed char)(ss >> 16);
    const signed char s3 = (signed char)(ss >> 24);

    #pragma unroll
    for (int it = 0; it < 8; it++) {
        int c = (tid >> 3) + it * 64;
        size_t gi = ((size_t)b << 19) + ((size_t)c << 10) + (t0 >> 2) + t4;
        float4 v = inp4[gi];
        // stash raw (pre-mask) values for gather extraction
        tile[c][t4 * 4 + 0] = v.x;
        tile[c][t4 * 4 + 1] = v.y;
        tile[c][t4 * 4 + 2] = v.z;
        tile[c][t4 * 4 + 3] = v.w;
        if (ss != -1) {                      // rare (~1.6% of valid (b,t))
            if (s0 >= 0) v.x = __ldg(mask_emb + s0 * C_CH + c);
            if (s1 >= 0) v.y = __ldg(mask_emb + s1 * C_CH + c);
            if (s2 >= 0) v.z = __ldg(mask_emb + s2 * C_CH + c);
            if (s3 >= 0) v.w = __ldg(mask_emb + s3 * C_CH + c);
        }
        out4[gi] = v;
    }
    __syncthreads();

    // extraction: one fully coalesced 512-float g_A row per target
    #pragma unroll 1
    for (int tloc = 0; tloc < TCH; tloc++) {
        int row = rowbuf[tloc];
        if (row >= 0)
            g_A[(size_t)row * FD + tid] = tf32r(tile[tid][tloc]);
    }
}

// ---------------------------------------------------------------------------
// Tensor-core GEMM (tf32 mma.sync), 2-stage cp.async double buffering.
// CTA tile 128x128, BK=32, 256 threads, warp grid 4(m) x 2(n).
// ---------------------------------------------------------------------------
#define GBK 32
#define GSTRIDE (GBK + 4)                       // 36 (x4B = 144B, 16B-aligned)
#define GEMM_SMEM_BYTES (2 * 2 * 128 * GSTRIDE * 4)   // 73728

__global__ void __launch_bounds__(256) k_gemm_tc(const float* __restrict__ bq,
                                                 float* __restrict__ res) {
    extern __shared__ __align__(16) float dsm[];
    float* Asm = dsm;                            // [2][128][GSTRIDE]
    float* Bsm = dsm + 2 * 128 * GSTRIDE;
    #define AS(s, r, c) Asm[(s) * 128 * GSTRIDE + (r) * GSTRIDE + (c)]
    #define BS(s, r, c) Bsm[(s) * 128 * GSTRIDE + (r) * GSTRIDE + (c)]

    const int tid  = threadIdx.x;
    const int warp = tid >> 5, lane = tid & 31;
    const int wm = warp & 3;       // 0..3 -> 32 rows each
    const int wn = warp >> 2;      // 0..1 -> 64 cols each
    const int m0 = blockIdx.x * 128;
    const int f0 = blockIdx.y * 128;

    const float* Ag = g_A + (size_t)m0 * FD;
    const float* Bg = g_B + (size_t)f0 * FD;

    const int lr  = tid >> 3;            // 0..31: load row group base
    const int lc4 = (tid & 7) << 2;      // 0,4,..,28

    float acc[2][8][4];
    #pragma unroll
    for (int mt = 0; mt < 2; mt++)
        #pragma unroll
        for (int nt = 0; nt < 8; nt++)
            #pragma unroll
            for (int q = 0; q < 4; q++) acc[mt][nt][q] = 0.f;

    const int row = lane >> 2;     // 0..7
    const int col = lane & 3;      // 0..3
    const int NIT = FD / GBK;      // 16

    // stage 0 prefetch
    #pragma unroll
    for (int p = 0; p < 4; p++) {
        int r = lr + p * 32;
        cp_async16(&AS(0, r, lc4), Ag + (size_t)r * FD + lc4);
        cp_async16(&BS(0, r, lc4), Bg + (size_t)r * FD + lc4);
    }
    asm volatile("cp.async.commit_group;\n");

    int buf = 0;
    for (int it = 0; it < NIT; it++) {
        if (it + 1 < NIT) {
            int k0 = (it + 1) * GBK;
            #pragma unroll
            for (int p = 0; p < 4; p++) {
                int r = lr + p * 32;
                cp_async16(&AS(buf ^ 1, r, lc4), Ag + (size_t)r * FD + k0 + lc4);
                cp_async16(&BS(buf ^ 1, r, lc4), Bg + (size_t)r * FD + k0 + lc4);
            }
            asm volatile("cp.async.commit_group;\n");
            asm volatile("cp.async.wait_group 1;\n");
        } else {
            asm volatile("cp.async.wait_group 0;\n");
        }
        __syncthreads();

        #pragma unroll
        for (int ks = 0; ks < GBK / 8; ks++) {
            const int kk = ks * 8;
            uint32_t a[2][4], bfr[8][2];
            #pragma unroll
            for (int mt = 0; mt < 2; mt++) {
                int mb = wm * 32 + mt * 16;
                a[mt][0] = __float_as_uint(AS(buf, mb + row,     kk + col));
                a[mt][1] = __float_as_uint(AS(buf, mb + row + 8, kk + col));
                a[mt][2] = __float_as_uint(AS(buf, mb + row,     kk + col + 4));
                a[mt][3] = __float_as_uint(AS(buf, mb + row + 8, kk + col + 4));
            }
            #pragma unroll
            for (int nt = 0; nt < 8; nt++) {
                int nb = wn * 64 + nt * 8;
                bfr[nt][0] = __float_as_uint(BS(buf, nb + row, kk + col));
                bfr[nt][1] = __float_as_uint(BS(buf, nb + row, kk + col + 4));
            }
            #pragma unroll
            for (int mt = 0; mt < 2; mt++)
                #pragma unroll
                for (int nt = 0; nt < 8; nt++) {
                    asm volatile(
                        "mma.sync.aligned.m16n8k8.row.col.f32.tf32.tf32.f32 "
                        "{%0,%1,%2,%3}, {%4,%5,%6,%7}, {%8,%9}, {%0,%1,%2,%3};\n"
                        : "+f"(acc[mt][nt][0]), "+f"(acc[mt][nt][1]),
                          "+f"(acc[mt][nt][2]), "+f"(acc[mt][nt][3])
                        : "r"(a[mt][0]), "r"(a[mt][1]), "r"(a[mt][2]), "r"(a[mt][3]),
                          "r"(bfr[nt][0]), "r"(bfr[nt][1]));
                }
        }
        __syncthreads();
        buf ^= 1;
    }

    const int colp = (lane & 3) * 2;
    #pragma unroll
    for (int mt = 0; mt < 2; mt++) {
        int m = m0 + wm * 32 + mt * 16 + row;
        #pragma unroll
        for (int nt = 0; nt < 8; nt++) {
            int f = f0 + wn * 64 + nt * 8 + colp;
            float b0 = __ldg(bq + f), b1 = __ldg(bq + f + 1);
            *(float2*)(res + (size_t)m       * FD + f) =
                make_float2(acc[mt][nt][0] + b0, acc[mt][nt][1] + b1);
            *(float2*)(res + (size_t)(m + 8) * FD + f) =
                make_float2(acc[mt][nt][2] + b0, acc[mt][nt][3] + b1);
        }
    }
    #undef AS
    #undef BS
}

// ---------------------------------------------------------------------------
extern "C" void kernel_launch(void* const* d_in, const int* in_sizes, int n_in,
                              void* d_out, int out_size) {
    (void)in_sizes; (void)n_in; (void)out_size;
    const float* inputs     = (const float*)d_in[0];
    const int*   seq_len    = (const int*)  d_in[1];
    const int*   pack_idx   = (const int*)  d_in[2];
    const int*   masked_idx = (const int*)  d_in[3];
    const int*   neg_idx    = (const int*)  d_in[4];
    const float* mask_emb   = (const float*)d_in[5];
    const float* Wq         = (const float*)d_in[6];
    const float* bq         = (const float*)d_in[7];

    float* out = (float*)d_out;
    float* res = out + OUT_MAIN_ELEMS;   // unmasked (1024x512) then negatives (10240x512)

    k_init<<<(N_B * W_LEN + 255) / 256, 256>>>();
    k_scatter<<<(M_ROWS + 255) / 256, 256>>>(masked_idx, neg_idx, pack_idx);
    k_prep_B<<<(FD * FD + 255) / 256, 256>>>(Wq);

    dim3 fgrid(W_LEN / TCH, N_B);
    k_fused<<<fgrid, 512>>>((const float4*)inputs, seq_len, mask_emb, (float4*)d_out);

    cudaFuncSetAttribute(k_gemm_tc, cudaFuncAttributeMaxDynamicSharedMemorySize,
                         GEMM_SMEM_BYTES);
    dim3 grid(M_ROWS / 128, FD / 128);
    k_gemm_tc<<<grid, 256, GEMM_SMEM_BYTES>>>(bq, res);
}

// round 10
// speedup vs baseline: 3.2442x; 1.1674x over previous
#include <cuda_runtime.h>
#include <cstdint>

#define N_B    16
#define C_CH   512
#define W_LEN  4096
#define NUM_MASKED 1024          // NUM_MASKS * MASK_WIDTH
#define M_ROWS 11264             // 1024 masked + 10240 negative rows
#define FD     512
#define OUT_MAIN_ELEMS ((size_t)N_B * C_CH * W_LEN)   // 33,554,432
#define TCH 32                   // t-chunk per fused block

// Scratch (device globals only — no allocation allowed)
__device__ float g_A[(size_t)M_ROWS * FD];                   // gathered A (tf32-rounded)
__device__ float g_B[(size_t)FD * FD];                       // Wq (tf32-rounded)
__device__ __align__(128) signed char g_slot[N_B * W_LEN];   // (b,t) -> mask row (0..3) or -1
__device__ int g_row[N_B * W_LEN];                           // (b,t) -> gemm row m or -1

__device__ __forceinline__ float tf32r(float x) {
    float y;
    asm("cvt.rna.tf32.f32 %0, %1;" : "=f"(y) : "f"(x));
    return y;
}

__device__ __forceinline__ void cp_async16(void* smem_dst, const void* gmem_src) {
    uint32_t s = (uint32_t)__cvta_generic_to_shared(smem_dst);
    asm volatile("cp.async.cg.shared.global [%0], [%1], 16;\n" :: "r"(s), "l"(gmem_src));
}

// ---------------------------------------------------------------------------
// Setup: tf32-round Wq into g_B; init lookup tables to -1  (one kernel)
// ---------------------------------------------------------------------------
__global__ void k_setup(const float* __restrict__ Wq) {
    int i = blockIdx.x * blockDim.x + threadIdx.x;   // grid covers FD*FD
    g_B[i] = tf32r(Wq[i]);
    if (i < N_B * W_LEN) g_row[i] = -1;
    if (i < (N_B * W_LEN) / 4) ((int*)g_slot)[i] = -1;
}

__global__ void k_scatter(const int* __restrict__ masked_idx,
                          const int* __restrict__ neg_idx,
                          const int* __restrict__ pack_idx) {
    int m = blockIdx.x * blockDim.x + threadIdx.x;
    if (m < M_ROWS) {
        int sel = (m < NUM_MASKED) ? masked_idx[m] : neg_idx[m - NUM_MASKED];
        int flat = pack_idx[sel];
        g_row[flat] = m;
        if (m < NUM_MASKED) g_slot[flat] = (signed char)(m & 3);
    }
}

// ---------------------------------------------------------------------------
// Fused streaming copy + mask-overwrite + zero-pad + direct A-gather.
// No smem, no barriers. Loads batched (MLP=8) before any store.
// ---------------------------------------------------------------------------
__global__ void __launch_bounds__(512) k_fused(const float4* __restrict__ inp4,
                                               const int* __restrict__ seq_len,
                                               const float* __restrict__ mask_emb,
                                               float4* __restrict__ out4) {
    const int b  = blockIdx.y;
    const int t0 = blockIdx.x * TCH;
    const int tid = threadIdx.x;
    const int len = __ldg(seq_len + b);
    const int t4  = tid & 7;                 // float4 group within chunk (fixed)
    const size_t base = ((size_t)b << 19) + (size_t)(t0 >> 2) + t4;
    const int c0 = tid >> 3;                 // first channel of this thread

    if (t0 >= len) {                         // fully padded chunk: zeros only
        const float4 z = make_float4(0.f, 0.f, 0.f, 0.f);
        #pragma unroll
        for (int it = 0; it < 8; it++)
            out4[base + ((size_t)(c0 + it * 64) << 10)] = z;
        return;
    }

    // loop-invariant per-thread metadata (4 consecutive t values)
    const int4 rows = *(const int4*)(g_row + b * W_LEN + t0 + t4 * 4);
    const bool anyrow = (rows.x & rows.y & rows.z & rows.w) != -1;
    const int ss = *(const int*)(g_slot + b * W_LEN + t0 + t4 * 4);

    // batched loads: 8 independent LDG.128 in flight
    float4 v[8];
    #pragma unroll
    for (int it = 0; it < 8; it++)
        v[it] = inp4[base + ((size_t)(c0 + it * 64) << 10)];

    if (anyrow) {                            // pre-mask values feed the GEMM
        #pragma unroll
        for (int it = 0; it < 8; it++) {
            int c = c0 + it * 64;
            if (rows.x >= 0) g_A[(size_t)rows.x * FD + c] = tf32r(v[it].x);
            if (rows.y >= 0) g_A[(size_t)rows.y * FD + c] = tf32r(v[it].y);
            if (rows.z >= 0) g_A[(size_t)rows.z * FD + c] = tf32r(v[it].z);
            if (rows.w >= 0) g_A[(size_t)rows.w * FD + c] = tf32r(v[it].w);
        }
    }
    if (ss != -1) {                          // rare mask overwrite (~1.6%)
        const signed char s0 = (signed char)(ss);
        const signed char s1 = (signed char)(ss >> 8);
        const signed char s2 = (signed char)(ss >> 16);
        const signed char s3 = (signed char)(ss >> 24);
        #pragma unroll
        for (int it = 0; it < 8; it++) {
            int c = c0 + it * 64;
            if (s0 >= 0) v[it].x = __ldg(mask_emb + s0 * C_CH + c);
            if (s1 >= 0) v[it].y = __ldg(mask_emb + s1 * C_CH + c);
            if (s2 >= 0) v[it].z = __ldg(mask_emb + s2 * C_CH + c);
            if (s3 >= 0) v[it].w = __ldg(mask_emb + s3 * C_CH + c);
        }
    }
    #pragma unroll
    for (int it = 0; it < 8; it++)
        out4[base + ((size_t)(c0 + it * 64) << 10)] = v[it];
}

// ---------------------------------------------------------------------------
// Tensor-core GEMM (tf32 mma.sync), 2-stage cp.async double buffering.
// CTA tile 128x64 (704 CTAs -> no 2-wave tail at t_big granularity).
// 256 threads, warp grid 4(m) x 2(n), warp tile 32x32.
// ---------------------------------------------------------------------------
#define GBM 128
#define GBN 64
#define GBK 32
#define GSTRIDE (GBK + 4)                       // 36 floats
#define A_SM (GBM * GSTRIDE)
#define B_SM (GBN * GSTRIDE)
#define GEMM_SMEM_BYTES (2 * (A_SM + B_SM) * 4)   // 55296

__global__ void __launch_bounds__(256, 3) k_gemm_tc(const float* __restrict__ bq,
                                                    float* __restrict__ res) {
    extern __shared__ __align__(16) float dsm[];
    float* Asm = dsm;                            // [2][GBM][GSTRIDE]
    float* Bsm = dsm + 2 * A_SM;                 // [2][GBN][GSTRIDE]
    #define AS(s, r, c) Asm[(s) * A_SM + (r) * GSTRIDE + (c)]
    #define BS(s, r, c) Bsm[(s) * B_SM + (r) * GSTRIDE + (c)]

    const int tid  = threadIdx.x;
    const int warp = tid >> 5, lane = tid & 31;
    const int wm = warp & 3;       // 0..3 -> 32 rows each
    const int wn = warp >> 2;      // 0..1 -> 32 cols each
    const int m0 = blockIdx.x * GBM;
    const int f0 = blockIdx.y * GBN;

    const float* Ag = g_A + (size_t)m0 * FD;
    const float* Bg = g_B + (size_t)f0 * FD;

    const int lr  = tid >> 3;            // 0..31
    const int lc4 = (tid & 7) << 2;      // 0,4,..,28

    float acc[2][4][4];
    #pragma unroll
    for (int mt = 0; mt < 2; mt++)
        #pragma unroll
        for (int nt = 0; nt < 4; nt++)
            #pragma unroll
            for (int q = 0; q < 4; q++) acc[mt][nt][q] = 0.f;

    const int row = lane >> 2;     // 0..7
    const int col = lane & 3;      // 0..3
    const int NIT = FD / GBK;      // 16

    // stage 0 prefetch
    #pragma unroll
    for (int p = 0; p < 4; p++) {
        int r = lr + p * 32;
        cp_async16(&AS(0, r, lc4), Ag + (size_t)r * FD + lc4);
    }
    #pragma unroll
    for (int p = 0; p < 2; p++) {
        int r = lr + p * 32;
        cp_async16(&BS(0, r, lc4), Bg + (size_t)r * FD + lc4);
    }
    asm volatile("cp.async.commit_group;\n");

    int buf = 0;
    for (int it = 0; it < NIT; it++) {
        if (it + 1 < NIT) {
            int k0 = (it + 1) * GBK;
            #pragma unroll
            for (int p = 0; p < 4; p++) {
                int r = lr + p * 32;
                cp_async16(&AS(buf ^ 1, r, lc4), Ag + (size_t)r * FD + k0 + lc4);
            }
            #pragma unroll
            for (int p = 0; p < 2; p++) {
                int r = lr + p * 32;
                cp_async16(&BS(buf ^ 1, r, lc4), Bg + (size_t)r * FD + k0 + lc4);
            }
            asm volatile("cp.async.commit_group;\n");
            asm volatile("cp.async.wait_group 1;\n");
        } else {
            asm volatile("cp.async.wait_group 0;\n");
        }
        __syncthreads();

        #pragma unroll
        for (int ks = 0; ks < GBK / 8; ks++) {
            const int kk = ks * 8;
            uint32_t a[2][4], bfr[4][2];
            #pragma unroll
            for (int mt = 0; mt < 2; mt++) {
                int mb = wm * 32 + mt * 16;
                a[mt][0] = __float_as_uint(AS(buf, mb + row,     kk + col));
                a[mt][1] = __float_as_uint(AS(buf, mb + row + 8, kk + col));
                a[mt][2] = __float_as_uint(AS(buf, mb + row,     kk + col + 4));
                a[mt][3] = __float_as_uint(AS(buf, mb + row + 8, kk + col + 4));
            }
            #pragma unroll
            for (int nt = 0; nt < 4; nt++) {
                int nb = wn * 32 + nt * 8;
                bfr[nt][0] = __float_as_uint(BS(buf, nb + row, kk + col));
                bfr[nt][1] = __float_as_uint(BS(buf, nb + row, kk + col + 4));
            }
            #pragma unroll
            for (int mt = 0; mt < 2; mt++)
                #pragma unroll
                for (int nt = 0; nt < 4; nt++) {
                    asm volatile(
                        "mma.sync.aligned.m16n8k8.row.col.f32.tf32.tf32.f32 "
                        "{%0,%1,%2,%3}, {%4,%5,%6,%7}, {%8,%9}, {%0,%1,%2,%3};\n"
                        : "+f"(acc[mt][nt][0]), "+f"(acc[mt][nt][1]),
                          "+f"(acc[mt][nt][2]), "+f"(acc[mt][nt][3])
                        : "r"(a[mt][0]), "r"(a[mt][1]), "r"(a[mt][2]), "r"(a[mt][3]),
                          "r"(bfr[nt][0]), "r"(bfr[nt][1]));
                }
        }
        __syncthreads();
        buf ^= 1;
    }

    const int colp = (lane & 3) * 2;
    #pragma unroll
    for (int mt = 0; mt < 2; mt++) {
        int m = m0 + wm * 32 + mt * 16 + row;
        #pragma unroll
        for (int nt = 0; nt < 4; nt++) {
            int f = f0 + wn * 32 + nt * 8 + colp;
            float b0 = __ldg(bq + f), b1 = __ldg(bq + f + 1);
            *(float2*)(res + (size_t)m       * FD + f) =
                make_float2(acc[mt][nt][0] + b0, acc[mt][nt][1] + b1);
            *(float2*)(res + (size_t)(m + 8) * FD + f) =
                make_float2(acc[mt][nt][2] + b0, acc[mt][nt][3] + b1);
        }
    }
    #undef AS
    #undef BS
}

// ---------------------------------------------------------------------------
extern "C" void kernel_launch(void* const* d_in, const int* in_sizes, int n_in,
                              void* d_out, int out_size) {
    (void)in_sizes; (void)n_in; (void)out_size;
    const float* inputs     = (const float*)d_in[0];
    const int*   seq_len    = (const int*)  d_in[1];
    const int*   pack_idx   = (const int*)  d_in[2];
    const int*   masked_idx = (const int*)  d_in[3];
    const int*   neg_idx    = (const int*)  d_in[4];
    const float* mask_emb   = (const float*)d_in[5];
    const float* Wq         = (const float*)d_in[6];
    const float* bq         = (const float*)d_in[7];

    float* out = (float*)d_out;
    float* res = out + OUT_MAIN_ELEMS;   // unmasked (1024x512) then negatives (10240x512)

    k_setup<<<(FD * FD) / 256, 256>>>(Wq);
    k_scatter<<<(M_ROWS + 255) / 256, 256>>>(masked_idx, neg_idx, pack_idx);

    dim3 fgrid(W_LEN / TCH, N_B);
    k_fused<<<fgrid, 512>>>((const float4*)inputs, seq_len, mask_emb, (float4*)d_out);

    cudaFuncSetAttribute(k_gemm_tc, cudaFuncAttributeMaxDynamicSharedMemorySize,
                         GEMM_SMEM_BYTES);
    dim3 grid(M_ROWS / GBM, FD / GBN);
    k_gemm_tc<<<grid, 256, GEMM_SMEM_BYTES>>>(bq, res);
}

// round 12
// speedup vs baseline: 4.3489x; 1.3405x over previous
#include <cuda_runtime.h>
#include <cuda_fp16.h>
#include <cstdint>

#define N_B    16
#define C_CH   512
#define W_LEN  4096
#define NUM_MASKED 1024          // NUM_MASKS * MASK_WIDTH
#define M_ROWS 11264             // 1024 masked + 10240 negative rows
#define FD     512
#define OUT_MAIN_ELEMS ((size_t)N_B * C_CH * W_LEN)   // 33,554,432
#define TCH 32                   // t-chunk per fused block

// Scratch (device globals only — no allocation allowed)
__device__ __half g_A[(size_t)M_ROWS * FD];                  // gathered A (fp16)
__device__ __half g_B[(size_t)FD * FD];                      // Wq (fp16)
__device__ __align__(128) signed char g_slot[N_B * W_LEN];   // (b,t) -> mask row or -1
__device__ int g_row[N_B * W_LEN];                           // (b,t) -> gemm row m or -1

__device__ __forceinline__ void cp_async16(void* smem_dst, const void* gmem_src) {
    uint32_t s = (uint32_t)__cvta_generic_to_shared(smem_dst);
    asm volatile("cp.async.cg.shared.global [%0], [%1], 16;\n" :: "r"(s), "l"(gmem_src));
}

__device__ __forceinline__ uint32_t smem_u32(const void* p) {
    return (uint32_t)__cvta_generic_to_shared(p);
}

__device__ __forceinline__ void ldsm_x4(uint32_t& r0, uint32_t& r1, uint32_t& r2,
                                        uint32_t& r3, uint32_t addr) {
    asm volatile("ldmatrix.sync.aligned.m8n8.x4.shared.b16 {%0,%1,%2,%3}, [%4];"
                 : "=r"(r0), "=r"(r1), "=r"(r2), "=r"(r3) : "r"(addr));
}

// ---------------------------------------------------------------------------
// Setup: fp16-round Wq into g_B; init lookup tables to -1  (one kernel)
// ---------------------------------------------------------------------------
__global__ void k_setup(const float* __restrict__ Wq) {
    int i = blockIdx.x * blockDim.x + threadIdx.x;   // grid covers FD*FD
    g_B[i] = __float2half_rn(Wq[i]);
    if (i < N_B * W_LEN) g_row[i] = -1;
    if (i < (N_B * W_LEN) / 4) ((int*)g_slot)[i] = -1;
}

__global__ void k_scatter(const int* __restrict__ masked_idx,
                          const int* __restrict__ neg_idx,
                          const int* __restrict__ pack_idx) {
    int m = blockIdx.x * blockDim.x + threadIdx.x;
    if (m < M_ROWS) {
        int sel = (m < NUM_MASKED) ? masked_idx[m] : neg_idx[m - NUM_MASKED];
        int flat = pack_idx[sel];
        g_row[flat] = m;
        if (m < NUM_MASKED) g_slot[flat] = (signed char)(m & 3);
    }
}

// ---------------------------------------------------------------------------
// Fused streaming copy + mask-overwrite + zero-pad + direct A-gather.
// No smem, no barriers. Loads batched (MLP=8) before any store.
// ---------------------------------------------------------------------------
__global__ void __launch_bounds__(512) k_fused(const float4* __restrict__ inp4,
                                               const int* __restrict__ seq_len,
                                               const float* __restrict__ mask_emb,
                                               float4* __restrict__ out4) {
    const int b  = blockIdx.y;
    const int t0 = blockIdx.x * TCH;
    const int tid = threadIdx.x;
    const int len = __ldg(seq_len + b);
    const int t4  = tid & 7;                 // float4 group within chunk (fixed)
    const size_t base = ((size_t)b << 19) + (size_t)(t0 >> 2) + t4;
    const int c0 = tid >> 3;                 // first channel of this thread

    if (t0 >= len) {                         // fully padded chunk: zeros only
        const float4 z = make_float4(0.f, 0.f, 0.f, 0.f);
        #pragma unroll
        for (int it = 0; it < 8; it++)
            out4[base + ((size_t)(c0 + it * 64) << 10)] = z;
        return;
    }

    // loop-invariant per-thread metadata (4 consecutive t values)
    const int4 rows = *(const int4*)(g_row + b * W_LEN + t0 + t4 * 4);
    const bool anyrow = (rows.x & rows.y & rows.z & rows.w) != -1;
    const int ss = *(const int*)(g_slot + b * W_LEN + t0 + t4 * 4);

    // batched loads: 8 independent LDG.128 in flight
    float4 v[8];
    #pragma unroll
    for (int it = 0; it < 8; it++)
        v[it] = inp4[base + ((size_t)(c0 + it * 64) << 10)];

    if (anyrow) {                            // pre-mask values feed the GEMM
        #pragma unroll
        for (int it = 0; it < 8; it++) {
            int c = c0 + it * 64;
            if (rows.x >= 0) g_A[(size_t)rows.x * FD + c] = __float2half_rn(v[it].x);
            if (rows.y >= 0) g_A[(size_t)rows.y * FD + c] = __float2half_rn(v[it].y);
            if (rows.z >= 0) g_A[(size_t)rows.z * FD + c] = __float2half_rn(v[it].z);
            if (rows.w >= 0) g_A[(size_t)rows.w * FD + c] = __float2half_rn(v[it].w);
        }
    }
    if (ss != -1) {                          // rare mask overwrite (~1.6%)
        const signed char s0 = (signed char)(ss);
        const signed char s1 = (signed char)(ss >> 8);
        const signed char s2 = (signed char)(ss >> 16);
        const signed char s3 = (signed char)(ss >> 24);
        #pragma unroll
        for (int it = 0; it < 8; it++) {
            int c = c0 + it * 64;
            if (s0 >= 0) v[it].x = __ldg(mask_emb + s0 * C_CH + c);
            if (s1 >= 0) v[it].y = __ldg(mask_emb + s1 * C_CH + c);
            if (s2 >= 0) v[it].z = __ldg(mask_emb + s2 * C_CH + c);
            if (s3 >= 0) v[it].w = __ldg(mask_emb + s3 * C_CH + c);
        }
    }
    #pragma unroll
    for (int it = 0; it < 8; it++)
        out4[base + ((size_t)(c0 + it * 64) << 10)] = v[it];
}

// ---------------------------------------------------------------------------
// fp16 tensor-core GEMM (mma.sync.m16n8k16, fp32 accum), ldmatrix frags,
// 2-stage cp.async. CTA tile 128x64, BK=64 halves, 8 warps (4m x 2n),
// warp tile 32x32.
// ---------------------------------------------------------------------------
#define GBM 128
#define GBN 64
#define GBK 64
#define SST (GBK + 8)                        // 72 halves = 144B row stride
#define A_SMH (GBM * SST)                    // halves per A stage
#define B_SMH (GBN * SST)
#define GEMM_SMEM_BYTES (2 * (A_SMH + B_SMH) * 2)   // 55296

__global__ void __launch_bounds__(256, 3) k_gemm_h(const float* __restrict__ bq,
                                                   float* __restrict__ res) {
    extern __shared__ __align__(16) __half hsm[];
    __half* Asm = hsm;                       // [2][GBM][SST]
    __half* Bsm = hsm + 2 * A_SMH;           // [2][GBN][SST]

    const int tid  = threadIdx.x;
    const int warp = tid >> 5, lane = tid & 31;
    const int wm = warp & 3;       // 0..3 -> 32 rows each
    const int wn = warp >> 2;      // 0..1 -> 32 cols each
    const int m0 = blockIdx.x * GBM;
    const int f0 = blockIdx.y * GBN;

    const __half* Ag = g_A + (size_t)m0 * FD;
    const __half* Bg = g_B + (size_t)f0 * FD;

    const int lr8 = tid >> 3;      // 0..31: row group for cp.async
    const int lk8 = (tid & 7) * 8; // half-offset 0,8,..,56

    float acc[2][4][4];
    #pragma unroll
    for (int mt = 0; mt < 2; mt++)
        #pragma unroll
        for (int nt = 0; nt < 4; nt++)
            #pragma unroll
            for (int q = 0; q < 4; q++) acc[mt][nt][q] = 0.f;

    // ldmatrix source addresses (byte offsets within a stage)
    const uint32_t a_base = smem_u32(Asm);
    const uint32_t b_base = smem_u32(Bsm);
    const int a_row = (lane & 15);           // + mb
    const int a_col = (lane >> 4) << 3;      // 0 or 8, + kk
    const int b_row = (lane & 7) + ((lane >> 4) << 3);   // + nb
    const int b_col = ((lane >> 3) & 1) << 3;            // 0 or 8, + kk

    const int NIT = FD / GBK;      // 8

    // stage 0 prefetch: A 128 rows x 4 chunks, B 64 rows x 4... (8 chunks/row of 16B? 64 halves=128B=8 chunks)
    #pragma unroll
    for (int p = 0; p < 4; p++) {            // A: 1024 chunks / 256 threads
        int f = tid + p * 256;
        int r = f >> 3;
        int c8 = (f & 7) * 8;
        cp_async16(Asm + r * SST + c8, Ag + (size_t)r * FD + c8);
    }
    #pragma unroll
    for (int p = 0; p < 2; p++) {            // B: 512 chunks
        int f = tid + p * 256;
        int r = f >> 3;
        int c8 = (f & 7) * 8;
        cp_async16(Bsm + r * SST + c8, Bg + (size_t)r * FD + c8);
    }
    asm volatile("cp.async.commit_group;\n");

    int buf = 0;
    for (int it = 0; it < NIT; it++) {
        if (it + 1 < NIT) {
            int k0 = (it + 1) * GBK;
            __half* Ad = Asm + (buf ^ 1) * A_SMH;
            __half* Bd = Bsm + (buf ^ 1) * B_SMH;
            #pragma unroll
            for (int p = 0; p < 4; p++) {
                int f = tid + p * 256;
                int r = f >> 3;
                int c8 = (f & 7) * 8;
                cp_async16(Ad + r * SST + c8, Ag + (size_t)r * FD + k0 + c8);
            }
            #pragma unroll
            for (int p = 0; p < 2; p++) {
                int f = tid + p * 256;
                int r = f >> 3;
                int c8 = (f & 7) * 8;
                cp_async16(Bd + r * SST + c8, Bg + (size_t)r * FD + k0 + c8);
            }
            asm volatile("cp.async.commit_group;\n");
            asm volatile("cp.async.wait_group 1;\n");
        } else {
            asm volatile("cp.async.wait_group 0;\n");
        }
        __syncthreads();

        const uint32_t a_st = a_base + buf * A_SMH * 2;
        const uint32_t b_st = b_base + buf * B_SMH * 2;

        #pragma unroll
        for (int ks = 0; ks < GBK / 16; ks++) {
            const int kk = ks * 16;
            uint32_t a[2][4], bf[4][2];
            #pragma unroll
            for (int mt = 0; mt < 2; mt++) {
                int mb = wm * 32 + mt * 16;
                uint32_t addr = a_st + ((mb + a_row) * SST + kk + a_col) * 2;
                ldsm_x4(a[mt][0], a[mt][1], a[mt][2], a[mt][3], addr);
            }
            #pragma unroll
            for (int ntp = 0; ntp < 2; ntp++) {
                int nb = wn * 32 + ntp * 16;
                uint32_t addr = b_st + ((nb + b_row) * SST + kk + b_col) * 2;
                ldsm_x4(bf[ntp*2][0], bf[ntp*2][1], bf[ntp*2+1][0], bf[ntp*2+1][1], addr);
            }
            #pragma unroll
            for (int mt = 0; mt < 2; mt++)
                #pragma unroll
                for (int nt = 0; nt < 4; nt++) {
                    asm volatile(
                        "mma.sync.aligned.m16n8k16.row.col.f32.f16.f16.f32 "
                        "{%0,%1,%2,%3}, {%4,%5,%6,%7}, {%8,%9}, {%0,%1,%2,%3};\n"
                        : "+f"(acc[mt][nt][0]), "+f"(acc[mt][nt][1]),
                          "+f"(acc[mt][nt][2]), "+f"(acc[mt][nt][3])
                        : "r"(a[mt][0]), "r"(a[mt][1]), "r"(a[mt][2]), "r"(a[mt][3]),
                          "r"(bf[nt][0]), "r"(bf[nt][1]));
                }
        }
        __syncthreads();
        buf ^= 1;
    }

    // epilogue: C frag at (row = lane>>2 [+8], col = 2*(lane&3) + {0,1})
    const int row  = lane >> 2;
    const int colp = (lane & 3) * 2;
    #pragma unroll
    for (int mt = 0; mt < 2; mt++) {
        int m = m0 + wm * 32 + mt * 16 + row;
        #pragma unroll
        for (int nt = 0; nt < 4; nt++) {
            int f = f0 + wn * 32 + nt * 8 + colp;
            float b0 = __ldg(bq + f), b1 = __ldg(bq + f + 1);
            *(float2*)(res + (size_t)m       * FD + f) =
                make_float2(acc[mt][nt][0] + b0, acc[mt][nt][1] + b1);
            *(float2*)(res + (size_t)(m + 8) * FD + f) =
                make_float2(acc[mt][nt][2] + b0, acc[mt][nt][3] + b1);
        }
    }
}

// ---------------------------------------------------------------------------
extern "C" void kernel_launch(void* const* d_in, const int* in_sizes, int n_in,
                              void* d_out, int out_size) {
    (void)in_sizes; (void)n_in; (void)out_size;
    const float* inputs     = (const float*)d_in[0];
    const int*   seq_len    = (const int*)  d_in[1];
    const int*   pack_idx   = (const int*)  d_in[2];
    const int*   masked_idx = (const int*)  d_in[3];
    const int*   neg_idx    = (const int*)  d_in[4];
    const float* mask_emb   = (const float*)d_in[5];
    const float* Wq         = (const float*)d_in[6];
    const float* bq         = (const float*)d_in[7];

    float* out = (float*)d_out;
    float* res = out + OUT_MAIN_ELEMS;   // unmasked (1024x512) then negatives (10240x512)

    k_setup<<<(FD * FD) / 256, 256>>>(Wq);
    k_scatter<<<(M_ROWS + 255) / 256, 256>>>(masked_idx, neg_idx, pack_idx);

    dim3 fgrid(W_LEN / TCH, N_B);
    k_fused<<<fgrid, 512>>>((const float4*)inputs, seq_len, mask_emb, (float4*)d_out);

    cudaFuncSetAttribute(k_gemm_h, cudaFuncAttributeMaxDynamicSharedMemorySize,
                         GEMM_SMEM_BYTES);
    dim3 grid(M_ROWS / GBM, FD / GBN);
    k_gemm_h<<<grid, 256, GEMM_SMEM_BYTES>>>(bq, res);
}